// round 15
// baseline (speedup 1.0000x reference)
#include <cuda_runtime.h>
#include <cuda_fp16.h>
#include <math.h>
#include <stdint.h>

// Problem constants
#define BATCH   2
#define S_LEN   2048
#define DM      1024
#define NHEADS  16
#define HDIM    64
#define MROWS   (BATCH * S_LEN)        // 4096
#define PCOLS   (4 * DM)               // 4096
#define ATT_SCALE 0.125f
#define LN_EPS  1e-5f

// Scratch (allocation-free rule: __device__ globals)
__device__ __half g_tok16 [(size_t)MROWS * DM];
__device__ __half g_Wt16  [(size_t)PCOLS * DM];     // W_qkuv^T fp16 (K-major)
__device__ __half g_Wo16T [(size_t)DM * DM];        // W_out^T fp16
__device__ __half g_P16   [(size_t)MROWS * PCOLS];  // silu(x@W), fp16
__device__ __half g_att16 [(size_t)MROWS * DM];
__device__ __half g_mask16[(size_t)BATCH * S_LEN * S_LEN];
__device__ float  g_inv   [(size_t)BATCH * S_LEN];  // rsqrt(max(rowsum,1))

// ---------------------------------------------------------------------------
// helpers
// ---------------------------------------------------------------------------
__device__ __forceinline__ float fsilu(float x) {
    float e, r;
    asm("ex2.approx.f32 %0, %1;" : "=f"(e) : "f"(-1.4426950408889634f * x));
    asm("rcp.approx.f32 %0, %1;" : "=f"(r) : "f"(1.0f + e));
    return x * r;
}
__device__ __forceinline__ void mma_f16(float c[4], const uint32_t a[4],
                                        uint32_t b0, uint32_t b1) {
    asm volatile(
        "mma.sync.aligned.m16n8k16.row.col.f32.f16.f16.f32 "
        "{%0,%1,%2,%3}, {%4,%5,%6,%7}, {%8,%9}, {%0,%1,%2,%3};\n"
        : "+f"(c[0]), "+f"(c[1]), "+f"(c[2]), "+f"(c[3])
        : "r"(a[0]), "r"(a[1]), "r"(a[2]), "r"(a[3]), "r"(b0), "r"(b1));
}
__device__ __forceinline__ void ldsm_x4(uint32_t addr, uint32_t r[4]) {
    asm volatile("ldmatrix.sync.aligned.m8n8.x4.shared.b16 {%0,%1,%2,%3}, [%4];"
        : "=r"(r[0]), "=r"(r[1]), "=r"(r[2]), "=r"(r[3]) : "r"(addr));
}
__device__ __forceinline__ void ldsm_x4t(uint32_t addr, uint32_t r[4]) {
    asm volatile("ldmatrix.sync.aligned.m8n8.x4.trans.shared.b16 {%0,%1,%2,%3}, [%4];"
        : "=r"(r[0]), "=r"(r[1]), "=r"(r[2]), "=r"(r[3]) : "r"(addr));
}
__device__ __forceinline__ void cp_async16(uint32_t saddr, const void* gptr) {
    asm volatile("cp.async.cg.shared.global [%0], [%1], 16;\n" :: "r"(saddr), "l"(gptr));
}
__device__ __forceinline__ void cp_commit() { asm volatile("cp.async.commit_group;\n"); }
template<int N>
__device__ __forceinline__ void cp_wait() {
    asm volatile("cp.async.wait_group %0;\n" :: "n"(N));
}
__device__ __forceinline__ uint32_t smem_u32_of(const void* p) {
    uint32_t a;
    asm("{ .reg .u64 tmp; cvta.to.shared.u64 tmp, %1; cvt.u32.u64 %0, tmp; }"
        : "=r"(a) : "l"(p));
    return a;
}
__device__ __forceinline__ uint32_t h2_u32(__half2 h) { return *(uint32_t*)&h; }
__device__ __forceinline__ __half2 u32_h2(uint32_t u) { return *(__half2*)&u; }

// ---------------------------------------------------------------------------
// prep kernels
// ---------------------------------------------------------------------------
__global__ void __launch_bounds__(256) cvt16_kernel(
    const float* __restrict__ in, __half* __restrict__ out, int n)
{
    int i = (blockIdx.x * 256 + threadIdx.x) * 4;
    if (i < n) {
        float4 v = *(const float4*)(in + i);
        *(__half2*)(out + i)     = __floats2half2_rn(v.x, v.y);
        *(__half2*)(out + i + 2) = __floats2half2_rn(v.z, v.w);
    }
}

__global__ void __launch_bounds__(256) transpose16_kernel(
    const float* __restrict__ W, __half* __restrict__ Wt, int K, int N)
{
    __shared__ float t[32][33];
    const int n0 = blockIdx.x * 32, k0 = blockIdx.y * 32;
    const int tx = threadIdx.x, ty = threadIdx.y;
#pragma unroll
    for (int i = 0; i < 32; i += 8)
        t[ty + i][tx] = W[(size_t)(k0 + ty + i) * N + n0 + tx];
    __syncthreads();
#pragma unroll
    for (int i = 0; i < 32; i += 8)
        Wt[(size_t)(n0 + ty + i) * K + k0 + tx] = __float2half_rn(t[tx][ty + i]);
}

__global__ void __launch_bounds__(256) mask_prep_kernel(
    const int* __restrict__ mask, __half* __restrict__ mask16, float* __restrict__ inv)
{
    const int row = blockIdx.x;
    const int tid = threadIdx.x;
    const int4* mr4 = (const int4*)(mask + (size_t)row * S_LEN);
    int4 x = mr4[tid * 2], y = mr4[tid * 2 + 1];
    int sum = x.x + x.y + x.z + x.w + y.x + y.y + y.z + y.w;

    uint4 o;
    o.x = h2_u32(__floats2half2_rn((float)x.x, (float)x.y));
    o.y = h2_u32(__floats2half2_rn((float)x.z, (float)x.w));
    o.z = h2_u32(__floats2half2_rn((float)y.x, (float)y.y));
    o.w = h2_u32(__floats2half2_rn((float)y.z, (float)y.w));
    *(uint4*)(mask16 + (size_t)row * S_LEN + tid * 8) = o;

#pragma unroll
    for (int d = 16; d > 0; d >>= 1) sum += __shfl_xor_sync(0xffffffffu, sum, d);
    __shared__ int ws[8];
    if ((tid & 31) == 0) ws[tid >> 5] = sum;
    __syncthreads();
    if (tid == 0) {
        int s = 0;
#pragma unroll
        for (int i = 0; i < 8; i++) s += ws[i];
        inv[row] = rsqrtf(fmaxf((float)s, 1.0f));
    }
}

// ---------------------------------------------------------------------------
// fp16 GEMM: C[M,N] = f(A[M,K] @ Bt[N,K]^T).
// CTA 128x256x32, 512 threads = 16 warps (4x4), warp tile 32x64.
// 4-stage cp.async; ldmatrix.x4 fragment loads.
// mode 0: C fp32.  mode 1: C = fp16(silu(.)).
// ---------------------------------------------------------------------------
#define G_AST   40
#define G_AH    (128 * G_AST)
#define G_BH    (256 * G_AST)
#define G_STG_H (G_AH + G_BH)
#define G_NSTG  4
#define GEMM_SMEM_BYTES (G_NSTG * G_STG_H * 2)   // 122880

__global__ void __launch_bounds__(512) gemm_f16_kernel(
    const __half* __restrict__ A, const __half* __restrict__ Bt, void* __restrict__ Cv,
    int M, int N, int K, int mode)
{
    extern __shared__ __align__(16) __half smh[];
    const int tid  = threadIdx.x;
    const int warp = tid >> 5, lane = tid & 31;
    const int g = lane >> 2, t = lane & 3;
    const int m0 = blockIdx.y * 128, n0 = blockIdx.x * 256;
    const int wm = (warp >> 2) * 32, wn = (warp & 3) * 64;
    const uint32_t smem_u32 = smem_u32_of(smh);
    const int nk = K >> 5;

    auto load_stage = [&](int ks, int s) {
        const uint32_t as_base = smem_u32 + (uint32_t)(s * G_STG_H) * 2u;
        const uint32_t bs_base = as_base + (uint32_t)G_AH * 2u;
        const int k0 = ks << 5;
        {
            int r = tid >> 2, c8 = (tid & 3) * 8;
            cp_async16(as_base + (uint32_t)(r * G_AST + c8) * 2u,
                       A + (size_t)(m0 + r) * K + k0 + c8);
        }
#pragma unroll
        for (int it = 0; it < 2; it++) {
            int idx = tid + it * 512;
            int r = idx >> 2, c8 = (idx & 3) * 8;
            cp_async16(bs_base + (uint32_t)(r * G_AST + c8) * 2u,
                       Bt + (size_t)(n0 + r) * K + k0 + c8);
        }
    };

    float acc[2][8][4];
#pragma unroll
    for (int mt = 0; mt < 2; mt++)
#pragma unroll
        for (int nt = 0; nt < 8; nt++)
#pragma unroll
            for (int i = 0; i < 4; i++) acc[mt][nt][i] = 0.0f;

#pragma unroll
    for (int s = 0; s < G_NSTG - 1; s++) { load_stage(s, s); cp_commit(); }

    const int a_row_l = lane & 15, a_col_l = (lane >> 4) * 8;
    const int b_row_l = ((lane >> 4) << 3) + (lane & 7);
    const int b_col_l = ((lane >> 3) & 1) * 8;

    for (int j = 0; j < nk; j++) {
        cp_wait<G_NSTG - 2>();
        __syncthreads();
        if (j + G_NSTG - 1 < nk) {
            load_stage(j + G_NSTG - 1, (j + G_NSTG - 1) & (G_NSTG - 1));
            cp_commit();
        }
        const uint32_t as_u32 = smem_u32 + (uint32_t)((j & (G_NSTG - 1)) * G_STG_H) * 2u;
        const uint32_t bs_u32 = as_u32 + (uint32_t)G_AH * 2u;

#pragma unroll
        for (int ks = 0; ks < 2; ks++) {
            uint32_t a[2][4], bb[8][4];
#pragma unroll
            for (int mt = 0; mt < 2; mt++) {
                uint32_t addr = as_u32 +
                    (uint32_t)((wm + mt * 16 + a_row_l) * G_AST + ks * 16 + a_col_l) * 2u;
                ldsm_x4(addr, a[mt]);
            }
#pragma unroll
            for (int jj = 0; jj < 4; jj++) {
                uint32_t addr = bs_u32 +
                    (uint32_t)((wn + jj * 16 + b_row_l) * G_AST + ks * 16 + b_col_l) * 2u;
                uint32_t r4[4];
                ldsm_x4(addr, r4);
                bb[2 * jj][0] = r4[0]; bb[2 * jj][1] = r4[1];
                bb[2 * jj + 1][0] = r4[2]; bb[2 * jj + 1][1] = r4[3];
            }
#pragma unroll
            for (int mt = 0; mt < 2; mt++)
#pragma unroll
                for (int nt = 0; nt < 8; nt++)
                    mma_f16(acc[mt][nt], a[mt], bb[nt][0], bb[nt][1]);
        }
    }

    if (mode == 1) {
        __half* C = (__half*)Cv;
#pragma unroll
        for (int mt = 0; mt < 2; mt++) {
            int row = m0 + wm + mt * 16 + g;
#pragma unroll
            for (int nt = 0; nt < 8; nt++) {
                int col = n0 + wn + nt * 8 + 2 * t;
                *(__half2*)(C + (size_t)row * N + col) =
                    __floats2half2_rn(fsilu(acc[mt][nt][0]), fsilu(acc[mt][nt][1]));
                *(__half2*)(C + (size_t)(row + 8) * N + col) =
                    __floats2half2_rn(fsilu(acc[mt][nt][2]), fsilu(acc[mt][nt][3]));
            }
        }
    } else {
        float* C = (float*)Cv;
#pragma unroll
        for (int mt = 0; mt < 2; mt++) {
            int row = m0 + wm + mt * 16 + g;
#pragma unroll
            for (int nt = 0; nt < 8; nt++) {
                int col = n0 + wn + nt * 8 + 2 * t;
                *(float2*)(C + (size_t)row * N + col) =
                    make_float2(acc[mt][nt][0], acc[mt][nt][1]);
                *(float2*)(C + (size_t)(row + 8) * N + col) =
                    make_float2(acc[mt][nt][2], acc[mt][nt][3]);
            }
        }
    }
}

// ---------------------------------------------------------------------------
// fp16 fused SiLU-attention + normalizer + LayerNorm(64) + gate.
// Per-batch: base pointers pre-offset by the caller. Grid (S/128, NHEADS),
// 256 threads = 8 warps, warp owns 16 q rows (round-7 best config).
// ---------------------------------------------------------------------------
#define AT_ST   72
#define AT_QH   (128 * AT_ST)
#define AT_KH   (64 * AT_ST)
#define AT_VH   (64 * AT_ST)
#define AT_STGH (AT_KH + AT_VH)
#define ATT_SMEM_BYTES ((AT_QH + 2 * AT_STGH) * 2)   // 55296

__global__ void __launch_bounds__(256, 2) attn_kernel(
    const __half* __restrict__ P16b, const __half* __restrict__ mask16b,
    const float* __restrict__ invb,
    const float* __restrict__ gamma, const float* __restrict__ beta,
    __half* __restrict__ att16b)
{
    extern __shared__ __align__(16) __half sh[];
    __half* Qs = sh;

    const int tid = threadIdx.x, warp = tid >> 5, lane = tid & 31;
    const int g = lane >> 2, t = lane & 3;
    const int h = blockIdx.y;
    const int q0 = blockIdx.x * 128;
    const uint32_t smem_u32 = smem_u32_of(sh);

    const __half* qb  = P16b + h * HDIM;
    const __half* kb_ = qb + DM;
    const __half* vb_ = qb + 2 * DM;
    const __half* gb_ = qb + 3 * DM;

#pragma unroll
    for (int it = 0; it < 4; it++) {
        int idx = tid + it * 256;
        int r = idx >> 3, c8 = (idx & 7) * 8;
        *(uint4*)&Qs[r * AT_ST + c8] = *(const uint4*)(qb + (size_t)(q0 + r) * PCOLS + c8);
    }

    auto load_kv = [&](int kblk, int s) {
        const uint32_t kbs = smem_u32 + (uint32_t)(AT_QH + s * AT_STGH) * 2u;
        const uint32_t vbs = kbs + (uint32_t)AT_KH * 2u;
        const int k0 = kblk * 64;
#pragma unroll
        for (int it = 0; it < 2; it++) {
            int idx = tid + it * 256;
            int r = idx >> 3, c8 = (idx & 7) * 8;
            cp_async16(kbs + (uint32_t)(r * AT_ST + c8) * 2u,
                       kb_ + (size_t)(k0 + r) * PCOLS + c8);
            cp_async16(vbs + (uint32_t)(r * AT_ST + c8) * 2u,
                       vb_ + (size_t)(k0 + r) * PCOLS + c8);
        }
    };
    load_kv(0, 0); cp_commit();

    float o[8][4];
#pragma unroll
    for (int nt = 0; nt < 8; nt++)
#pragma unroll
        for (int i = 0; i < 4; i++) o[nt][i] = 0.0f;

    const int lrow = warp * 16 + g;
    const int a_row_l = lane & 15, a_col_l = (lane >> 4) * 8;
    const int b_row_l = ((lane >> 4) << 3) + (lane & 7);
    const int b_col_l = ((lane >> 3) & 1) * 8;

    for (int kb = 0; kb < 32; kb++) {
        cp_wait<0>();
        __syncthreads();
        if (kb + 1 < 32) { load_kv(kb + 1, (kb + 1) & 1); cp_commit(); }

        const uint32_t k_u32 = smem_u32 + (uint32_t)(AT_QH + (kb & 1) * AT_STGH) * 2u;
        const uint32_t v_u32 = k_u32 + (uint32_t)AT_KH * 2u;

        // ---- prefetch mask (consumed after S-mma; latency hidden) ----
        uint32_t pm0[8], pm1[8];
#pragma unroll
        for (int nt = 0; nt < 8; nt++) {
            const __half* mp = mask16b + (size_t)(q0 + lrow) * S_LEN + kb * 64 + nt * 8 + 2 * t;
            pm0[nt] = *(const uint32_t*)mp;
            pm1[nt] = *(const uint32_t*)(mp + 8 * S_LEN);
        }

        // ---- S = Q @ K^T ----
        float s[8][4];
#pragma unroll
        for (int nt = 0; nt < 8; nt++)
#pragma unroll
            for (int i = 0; i < 4; i++) s[nt][i] = 0.0f;

#pragma unroll
        for (int ks = 0; ks < 4; ks++) {
            uint32_t a[4];
            ldsm_x4(smem_u32 +
                (uint32_t)((warp * 16 + a_row_l) * AT_ST + ks * 16 + a_col_l) * 2u, a);
#pragma unroll
            for (int jj = 0; jj < 4; jj++) {
                uint32_t r4[4];
                ldsm_x4(k_u32 +
                    (uint32_t)((jj * 16 + b_row_l) * AT_ST + ks * 16 + b_col_l) * 2u, r4);
                mma_f16(s[2 * jj],     a, r4[0], r4[1]);
                mma_f16(s[2 * jj + 1], a, r4[2], r4[3]);
            }
        }

        // ---- silu * mask -> packed fp16 A-frags ----
        uint32_t p0[8], p1[8];
#pragma unroll
        for (int nt = 0; nt < 8; nt++) {
            __half2 v01 = __floats2half2_rn(fsilu(s[nt][0] * ATT_SCALE),
                                            fsilu(s[nt][1] * ATT_SCALE));
            __half2 v23 = __floats2half2_rn(fsilu(s[nt][2] * ATT_SCALE),
                                            fsilu(s[nt][3] * ATT_SCALE));
            p0[nt] = h2_u32(__hmul2(v01, u32_h2(pm0[nt])));
            p1[nt] = h2_u32(__hmul2(v23, u32_h2(pm1[nt])));
        }

        // ---- O += S @ V  (V frags via ldmatrix.x4.trans) ----
#pragma unroll
        for (int kk = 0; kk < 4; kk++) {
            uint32_t a[4] = { p0[2 * kk], p1[2 * kk], p0[2 * kk + 1], p1[2 * kk + 1] };
#pragma unroll
            for (int jj = 0; jj < 4; jj++) {
                uint32_t r4[4];
                ldsm_x4t(v_u32 +
                    (uint32_t)((16 * kk + a_row_l) * AT_ST + jj * 16 + a_col_l) * 2u, r4);
                mma_f16(o[2 * jj],     a, r4[0], r4[1]);
                mma_f16(o[2 * jj + 1], a, r4[2], r4[3]);
            }
        }
    }

    // ---- normalizer + LayerNorm(64) + gate + store ----
    const float inv0 = invb[q0 + lrow];
    const float inv1 = invb[q0 + lrow + 8];

    float sum0 = 0.f, sq0 = 0.f, sum1 = 0.f, sq1 = 0.f;
#pragma unroll
    for (int nt = 0; nt < 8; nt++) {
        o[nt][0] *= inv0; o[nt][1] *= inv0;
        o[nt][2] *= inv1; o[nt][3] *= inv1;
        sum0 += o[nt][0] + o[nt][1];
        sq0  += o[nt][0] * o[nt][0] + o[nt][1] * o[nt][1];
        sum1 += o[nt][2] + o[nt][3];
        sq1  += o[nt][2] * o[nt][2] + o[nt][3] * o[nt][3];
    }
    sum0 += __shfl_xor_sync(0xffffffffu, sum0, 1);
    sum0 += __shfl_xor_sync(0xffffffffu, sum0, 2);
    sq0  += __shfl_xor_sync(0xffffffffu, sq0, 1);
    sq0  += __shfl_xor_sync(0xffffffffu, sq0, 2);
    sum1 += __shfl_xor_sync(0xffffffffu, sum1, 1);
    sum1 += __shfl_xor_sync(0xffffffffu, sum1, 2);
    sq1  += __shfl_xor_sync(0xffffffffu, sq1, 1);
    sq1  += __shfl_xor_sync(0xffffffffu, sq1, 2);

    const float mu0 = sum0 * (1.0f / 64.0f);
    const float mu1 = sum1 * (1.0f / 64.0f);
    const float rs0 = rsqrtf(sq0 * (1.0f / 64.0f) - mu0 * mu0 + LN_EPS);
    const float rs1 = rsqrtf(sq1 * (1.0f / 64.0f) - mu1 * mu1 + LN_EPS);

    const int grow0 = q0 + lrow, grow1 = grow0 + 8;
#pragma unroll
    for (int nt = 0; nt < 8; nt++) {
        const int d = nt * 8 + 2 * t;
        const float ga0 = gamma[d], ga1 = gamma[d + 1];
        const float be0 = beta[d],  be1 = beta[d + 1];
        float2 gv0 = __half22float2(*(const __half2*)(gb_ + (size_t)grow0 * PCOLS + d));
        float2 gv1 = __half22float2(*(const __half2*)(gb_ + (size_t)grow1 * PCOLS + d));
        float w0 = ((o[nt][0] - mu0) * rs0 * ga0 + be0) * gv0.x;
        float w1 = ((o[nt][1] - mu0) * rs0 * ga1 + be1) * gv0.y;
        float w2 = ((o[nt][2] - mu1) * rs1 * ga0 + be0) * gv1.x;
        float w3 = ((o[nt][3] - mu1) * rs1 * ga1 + be1) * gv1.y;
        *(__half2*)(att16b + (size_t)grow0 * DM + h * HDIM + d) = __floats2half2_rn(w0, w1);
        *(__half2*)(att16b + (size_t)grow1 * DM + h * HDIM + d) = __floats2half2_rn(w2, w3);
    }
}

// ---------------------------------------------------------------------------
// Launch: THREE streams; cvt16 split per batch so both heavy chains start
// at ~4.6us (transposeW latency) instead of ~7.2us (full cvt16).
//   s2  : cvt16(b1) -> evC1 -> mask_prep -> evM -> transposeWo -> evO
//   s1  : transposeW -> [wait evC1] b1 chain -> evB
//   main: cvt16(b0) -> [wait evW] b0 chain -> [wait evB]
// ---------------------------------------------------------------------------
extern "C" void kernel_launch(void* const* d_in, const int* in_sizes, int n_in,
                              void* d_out, int out_size)
{
    const float* tokens = (const float*)d_in[0];
    const int*   mask   = (const int*)d_in[1];
    const float* Wqkuv  = (const float*)d_in[2];
    const float* Wout   = (const float*)d_in[3];
    const float* gamma  = (const float*)d_in[4];
    const float* beta   = (const float*)d_in[5];
    float* out = (float*)d_out;

    __half *tok16, *Wt16, *Wo16T, *P16, *att16, *mask16;
    float* inv;
    cudaGetSymbolAddress((void**)&tok16,  g_tok16);
    cudaGetSymbolAddress((void**)&Wt16,   g_Wt16);
    cudaGetSymbolAddress((void**)&Wo16T,  g_Wo16T);
    cudaGetSymbolAddress((void**)&P16,    g_P16);
    cudaGetSymbolAddress((void**)&att16,  g_att16);
    cudaGetSymbolAddress((void**)&mask16, g_mask16);
    cudaGetSymbolAddress((void**)&inv,    g_inv);

    cudaFuncSetAttribute(gemm_f16_kernel, cudaFuncAttributeMaxDynamicSharedMemorySize,
                         GEMM_SMEM_BYTES);
    cudaFuncSetAttribute(attn_kernel, cudaFuncAttributeMaxDynamicSharedMemorySize,
                         ATT_SMEM_BYTES);

    // one-time host-handle setup (host handles only; no device memory)
    static cudaStream_t s1 = nullptr, s2 = nullptr;
    static cudaEvent_t evF = nullptr, evC1 = nullptr, evW = nullptr,
                       evM = nullptr, evO = nullptr, evB = nullptr;
    if (s1 == nullptr) {
        cudaStreamCreateWithFlags(&s1, cudaStreamNonBlocking);
        cudaStreamCreateWithFlags(&s2, cudaStreamNonBlocking);
        cudaEventCreateWithFlags(&evF, cudaEventDisableTiming);
        cudaEventCreateWithFlags(&evC1, cudaEventDisableTiming);
        cudaEventCreateWithFlags(&evW, cudaEventDisableTiming);
        cudaEventCreateWithFlags(&evM, cudaEventDisableTiming);
        cudaEventCreateWithFlags(&evO, cudaEventDisableTiming);
        cudaEventCreateWithFlags(&evB, cudaEventDisableTiming);
    }

    const size_t tokB = (size_t)S_LEN * DM;        // per-batch token elems
    const size_t pB   = (size_t)S_LEN * PCOLS;     // per-batch P elems
    const size_t mB   = (size_t)S_LEN * S_LEN;     // per-batch mask elems

    // fork
    cudaEventRecord(evF, 0);
    cudaStreamWaitEvent(s1, evF, 0);
    cudaStreamWaitEvent(s2, evF, 0);

    // ---- s2: cvt16(b1), then prep-only tail ----
    cvt16_kernel<<<(int)(tokB / 1024), 256, 0, s2>>>(
        tokens + tokB, tok16 + tokB, (int)tokB);
    cudaEventRecord(evC1, s2);
    mask_prep_kernel<<<BATCH * S_LEN, 256, 0, s2>>>(mask, mask16, inv);
    cudaEventRecord(evM, s2);
    transpose16_kernel<<<dim3(DM / 32, DM / 32), dim3(32, 8), 0, s2>>>(
        Wout, Wo16T, DM, DM);
    cudaEventRecord(evO, s2);

    // ---- s1: W transpose, then the full b1 chain ----
    transpose16_kernel<<<dim3(PCOLS / 32, DM / 32), dim3(32, 8), 0, s1>>>(
        Wqkuv, Wt16, DM, PCOLS);
    cudaEventRecord(evW, s1);

    cudaStreamWaitEvent(s1, evC1, 0);
    gemm_f16_kernel<<<dim3(PCOLS / 256, S_LEN / 128), 512, GEMM_SMEM_BYTES, s1>>>(
        tok16 + tokB, Wt16, P16 + pB, S_LEN, PCOLS, DM, 1);
    cudaStreamWaitEvent(s1, evM, 0);
    attn_kernel<<<dim3(S_LEN / 128, NHEADS), 256, ATT_SMEM_BYTES, s1>>>(
        P16 + pB, mask16 + mB, inv + S_LEN, gamma, beta, att16 + tokB);
    cudaStreamWaitEvent(s1, evO, 0);
    gemm_f16_kernel<<<dim3(DM / 256, S_LEN / 128), 512, GEMM_SMEM_BYTES, s1>>>(
        att16 + tokB, Wo16T, out + tokB, S_LEN, DM, DM, 0);
    cudaEventRecord(evB, s1);

    // ---- main: cvt16(b0), then the b0 chain ----
    cvt16_kernel<<<(int)(tokB / 1024), 256>>>(tokens, tok16, (int)tokB);

    cudaStreamWaitEvent(0, evW, 0);
    gemm_f16_kernel<<<dim3(PCOLS / 256, S_LEN / 128), 512, GEMM_SMEM_BYTES>>>(
        tok16, Wt16, P16, S_LEN, PCOLS, DM, 1);
    cudaStreamWaitEvent(0, evM, 0);
    attn_kernel<<<dim3(S_LEN / 128, NHEADS), 256, ATT_SMEM_BYTES>>>(
        P16, mask16, inv, gamma, beta, att16);
    cudaStreamWaitEvent(0, evO, 0);
    gemm_f16_kernel<<<dim3(DM / 256, S_LEN / 128), 512, GEMM_SMEM_BYTES>>>(
        att16, Wo16T, out, S_LEN, DM, DM, 0);

    // join
    cudaStreamWaitEvent(0, evB, 0);
}

// round 16
// speedup vs baseline: 1.0377x; 1.0377x over previous
#include <cuda_runtime.h>
#include <cuda_fp16.h>
#include <math.h>
#include <stdint.h>

// Problem constants
#define BATCH   2
#define S_LEN   2048
#define DM      1024
#define NHEADS  16
#define HDIM    64
#define MROWS   (BATCH * S_LEN)        // 4096
#define PCOLS   (4 * DM)               // 4096
#define ATT_SCALE 0.125f
#define LN_EPS  1e-5f

// Scratch (allocation-free rule: __device__ globals)
__device__ __half g_tok16 [(size_t)MROWS * DM];
__device__ __half g_Wt16  [(size_t)PCOLS * DM];     // W_qkuv^T fp16 (K-major)
__device__ __half g_Wo16T [(size_t)DM * DM];        // W_out^T fp16
__device__ __half g_P16   [(size_t)MROWS * PCOLS];  // silu(x@W), fp16
__device__ __half g_att16 [(size_t)MROWS * DM];
__device__ __half g_mask16[(size_t)BATCH * S_LEN * S_LEN];
__device__ float  g_inv   [(size_t)BATCH * S_LEN];  // rsqrt(max(rowsum,1))

// ---------------------------------------------------------------------------
// helpers
// ---------------------------------------------------------------------------
__device__ __forceinline__ float fsilu(float x) {
    float e, r;
    asm("ex2.approx.f32 %0, %1;" : "=f"(e) : "f"(-1.4426950408889634f * x));
    asm("rcp.approx.f32 %0, %1;" : "=f"(r) : "f"(1.0f + e));
    return x * r;
}
__device__ __forceinline__ void mma_f16(float c[4], const uint32_t a[4],
                                        uint32_t b0, uint32_t b1) {
    asm volatile(
        "mma.sync.aligned.m16n8k16.row.col.f32.f16.f16.f32 "
        "{%0,%1,%2,%3}, {%4,%5,%6,%7}, {%8,%9}, {%0,%1,%2,%3};\n"
        : "+f"(c[0]), "+f"(c[1]), "+f"(c[2]), "+f"(c[3])
        : "r"(a[0]), "r"(a[1]), "r"(a[2]), "r"(a[3]), "r"(b0), "r"(b1));
}
__device__ __forceinline__ void ldsm_x4(uint32_t addr, uint32_t r[4]) {
    asm volatile("ldmatrix.sync.aligned.m8n8.x4.shared.b16 {%0,%1,%2,%3}, [%4];"
        : "=r"(r[0]), "=r"(r[1]), "=r"(r[2]), "=r"(r[3]) : "r"(addr));
}
__device__ __forceinline__ void ldsm_x4t(uint32_t addr, uint32_t r[4]) {
    asm volatile("ldmatrix.sync.aligned.m8n8.x4.trans.shared.b16 {%0,%1,%2,%3}, [%4];"
        : "=r"(r[0]), "=r"(r[1]), "=r"(r[2]), "=r"(r[3]) : "r"(addr));
}
__device__ __forceinline__ void cp_async16(uint32_t saddr, const void* gptr) {
    asm volatile("cp.async.cg.shared.global [%0], [%1], 16;\n" :: "r"(saddr), "l"(gptr));
}
__device__ __forceinline__ void cp_commit() { asm volatile("cp.async.commit_group;\n"); }
template<int N>
__device__ __forceinline__ void cp_wait() {
    asm volatile("cp.async.wait_group %0;\n" :: "n"(N));
}
__device__ __forceinline__ uint32_t smem_u32_of(const void* p) {
    uint32_t a;
    asm("{ .reg .u64 tmp; cvta.to.shared.u64 tmp, %1; cvt.u32.u64 %0, tmp; }"
        : "=r"(a) : "l"(p));
    return a;
}
__device__ __forceinline__ uint32_t h2_u32(__half2 h) { return *(uint32_t*)&h; }
__device__ __forceinline__ __half2 u32_h2(uint32_t u) { return *(__half2*)&u; }

// ---------------------------------------------------------------------------
// prep kernels
// ---------------------------------------------------------------------------
__global__ void __launch_bounds__(256) cvt16_kernel(
    const float* __restrict__ in, __half* __restrict__ out, int n)
{
    int i = (blockIdx.x * 256 + threadIdx.x) * 4;
    if (i < n) {
        float4 v = *(const float4*)(in + i);
        *(__half2*)(out + i)     = __floats2half2_rn(v.x, v.y);
        *(__half2*)(out + i + 2) = __floats2half2_rn(v.z, v.w);
    }
}

__global__ void __launch_bounds__(256) transpose16_kernel(
    const float* __restrict__ W, __half* __restrict__ Wt, int K, int N)
{
    __shared__ float t[32][33];
    const int n0 = blockIdx.x * 32, k0 = blockIdx.y * 32;
    const int tx = threadIdx.x, ty = threadIdx.y;
#pragma unroll
    for (int i = 0; i < 32; i += 8)
        t[ty + i][tx] = W[(size_t)(k0 + ty + i) * N + n0 + tx];
    __syncthreads();
#pragma unroll
    for (int i = 0; i < 32; i += 8)
        Wt[(size_t)(n0 + ty + i) * K + k0 + tx] = __float2half_rn(t[tx][ty + i]);
}

__global__ void __launch_bounds__(256) mask_prep_kernel(
    const int* __restrict__ mask, __half* __restrict__ mask16, float* __restrict__ inv)
{
    const int row = blockIdx.x;
    const int tid = threadIdx.x;
    const int4* mr4 = (const int4*)(mask + (size_t)row * S_LEN);
    int4 x = mr4[tid * 2], y = mr4[tid * 2 + 1];
    int sum = x.x + x.y + x.z + x.w + y.x + y.y + y.z + y.w;

    uint4 o;
    o.x = h2_u32(__floats2half2_rn((float)x.x, (float)x.y));
    o.y = h2_u32(__floats2half2_rn((float)x.z, (float)x.w));
    o.z = h2_u32(__floats2half2_rn((float)y.x, (float)y.y));
    o.w = h2_u32(__floats2half2_rn((float)y.z, (float)y.w));
    *(uint4*)(mask16 + (size_t)row * S_LEN + tid * 8) = o;

#pragma unroll
    for (int d = 16; d > 0; d >>= 1) sum += __shfl_xor_sync(0xffffffffu, sum, d);
    __shared__ int ws[8];
    if ((tid & 31) == 0) ws[tid >> 5] = sum;
    __syncthreads();
    if (tid == 0) {
        int s = 0;
#pragma unroll
        for (int i = 0; i < 8; i++) s += ws[i];
        inv[row] = rsqrtf(fmaxf((float)s, 1.0f));
    }
}

// ---------------------------------------------------------------------------
// fp16 GEMM (wide): C[M,N] = f(A[M,K] @ Bt[N,K]^T).
// CTA 128x256x32, 512 threads = 16 warps (4x4), warp tile 32x64.
// 4-stage cp.async; ldmatrix.x4 fragment loads.
// mode 0: C fp32.  mode 1: C = fp16(silu(.)).
// ---------------------------------------------------------------------------
#define G_AST   40
#define G_AH    (128 * G_AST)
#define G_BH    (256 * G_AST)
#define G_STG_H (G_AH + G_BH)
#define G_NSTG  4
#define GEMM_SMEM_BYTES (G_NSTG * G_STG_H * 2)   // 122880

__global__ void __launch_bounds__(512) gemm_f16_kernel(
    const __half* __restrict__ A, const __half* __restrict__ Bt, void* __restrict__ Cv,
    int M, int N, int K, int mode)
{
    extern __shared__ __align__(16) __half smh[];
    const int tid  = threadIdx.x;
    const int warp = tid >> 5, lane = tid & 31;
    const int g = lane >> 2, t = lane & 3;
    const int m0 = blockIdx.y * 128, n0 = blockIdx.x * 256;
    const int wm = (warp >> 2) * 32, wn = (warp & 3) * 64;
    const uint32_t smem_u32 = smem_u32_of(smh);
    const int nk = K >> 5;

    auto load_stage = [&](int ks, int s) {
        const uint32_t as_base = smem_u32 + (uint32_t)(s * G_STG_H) * 2u;
        const uint32_t bs_base = as_base + (uint32_t)G_AH * 2u;
        const int k0 = ks << 5;
        {
            int r = tid >> 2, c8 = (tid & 3) * 8;
            cp_async16(as_base + (uint32_t)(r * G_AST + c8) * 2u,
                       A + (size_t)(m0 + r) * K + k0 + c8);
        }
#pragma unroll
        for (int it = 0; it < 2; it++) {
            int idx = tid + it * 512;
            int r = idx >> 2, c8 = (idx & 3) * 8;
            cp_async16(bs_base + (uint32_t)(r * G_AST + c8) * 2u,
                       Bt + (size_t)(n0 + r) * K + k0 + c8);
        }
    };

    float acc[2][8][4];
#pragma unroll
    for (int mt = 0; mt < 2; mt++)
#pragma unroll
        for (int nt = 0; nt < 8; nt++)
#pragma unroll
            for (int i = 0; i < 4; i++) acc[mt][nt][i] = 0.0f;

#pragma unroll
    for (int s = 0; s < G_NSTG - 1; s++) { load_stage(s, s); cp_commit(); }

    const int a_row_l = lane & 15, a_col_l = (lane >> 4) * 8;
    const int b_row_l = ((lane >> 4) << 3) + (lane & 7);
    const int b_col_l = ((lane >> 3) & 1) * 8;

    for (int j = 0; j < nk; j++) {
        cp_wait<G_NSTG - 2>();
        __syncthreads();
        if (j + G_NSTG - 1 < nk) {
            load_stage(j + G_NSTG - 1, (j + G_NSTG - 1) & (G_NSTG - 1));
            cp_commit();
        }
        const uint32_t as_u32 = smem_u32 + (uint32_t)((j & (G_NSTG - 1)) * G_STG_H) * 2u;
        const uint32_t bs_u32 = as_u32 + (uint32_t)G_AH * 2u;

#pragma unroll
        for (int ks = 0; ks < 2; ks++) {
            uint32_t a[2][4], bb[8][4];
#pragma unroll
            for (int mt = 0; mt < 2; mt++) {
                uint32_t addr = as_u32 +
                    (uint32_t)((wm + mt * 16 + a_row_l) * G_AST + ks * 16 + a_col_l) * 2u;
                ldsm_x4(addr, a[mt]);
            }
#pragma unroll
            for (int jj = 0; jj < 4; jj++) {
                uint32_t addr = bs_u32 +
                    (uint32_t)((wn + jj * 16 + b_row_l) * G_AST + ks * 16 + b_col_l) * 2u;
                uint32_t r4[4];
                ldsm_x4(addr, r4);
                bb[2 * jj][0] = r4[0]; bb[2 * jj][1] = r4[1];
                bb[2 * jj + 1][0] = r4[2]; bb[2 * jj + 1][1] = r4[3];
            }
#pragma unroll
            for (int mt = 0; mt < 2; mt++)
#pragma unroll
                for (int nt = 0; nt < 8; nt++)
                    mma_f16(acc[mt][nt], a[mt], bb[nt][0], bb[nt][1]);
        }
    }

    if (mode == 1) {
        __half* C = (__half*)Cv;
#pragma unroll
        for (int mt = 0; mt < 2; mt++) {
            int row = m0 + wm + mt * 16 + g;
#pragma unroll
            for (int nt = 0; nt < 8; nt++) {
                int col = n0 + wn + nt * 8 + 2 * t;
                *(__half2*)(C + (size_t)row * N + col) =
                    __floats2half2_rn(fsilu(acc[mt][nt][0]), fsilu(acc[mt][nt][1]));
                *(__half2*)(C + (size_t)(row + 8) * N + col) =
                    __floats2half2_rn(fsilu(acc[mt][nt][2]), fsilu(acc[mt][nt][3]));
            }
        }
    } else {
        float* C = (float*)Cv;
#pragma unroll
        for (int mt = 0; mt < 2; mt++) {
            int row = m0 + wm + mt * 16 + g;
#pragma unroll
            for (int nt = 0; nt < 8; nt++) {
                int col = n0 + wn + nt * 8 + 2 * t;
                *(float2*)(C + (size_t)row * N + col) =
                    make_float2(acc[mt][nt][0], acc[mt][nt][1]);
                *(float2*)(C + (size_t)(row + 8) * N + col) =
                    make_float2(acc[mt][nt][2], acc[mt][nt][3]);
            }
        }
    }
}

// ---------------------------------------------------------------------------
// fp16 GEMM (narrow, for GEMM3): C[M,N] = A[M,K] @ Bt[N,K]^T, fp32 out.
// CTA 128x128x32, 256 threads = 8 warps (4x2), warp tile 32x64 — same
// warp-level code and per-element k-order as the wide kernel (numerics
// identical). 2 CTAs/SM -> 2x CTA count fills the chip for small N.
// ---------------------------------------------------------------------------
#define G3_AH    (128 * G_AST)
#define G3_STG_H (2 * G3_AH)              // A + B, 10240 halves/stage
#define G3_SMEM_BYTES (G_NSTG * G3_STG_H * 2)   // 81920

__global__ void __launch_bounds__(256, 2) gemm_f16_n128_kernel(
    const __half* __restrict__ A, const __half* __restrict__ Bt, float* __restrict__ C,
    int M, int N, int K)
{
    extern __shared__ __align__(16) __half smh[];
    const int tid  = threadIdx.x;
    const int warp = tid >> 5, lane = tid & 31;
    const int g = lane >> 2, t = lane & 3;
    const int m0 = blockIdx.y * 128, n0 = blockIdx.x * 128;
    const int wm = (warp >> 1) * 32, wn = (warp & 1) * 64;
    const uint32_t smem_u32 = smem_u32_of(smh);
    const int nk = K >> 5;

    auto load_stage = [&](int ks, int s) {
        const uint32_t as_base = smem_u32 + (uint32_t)(s * G3_STG_H) * 2u;
        const uint32_t bs_base = as_base + (uint32_t)G3_AH * 2u;
        const int k0 = ks << 5;
#pragma unroll
        for (int it = 0; it < 2; it++) {     // A: 128x32 halves = 512 chunks
            int idx = tid + it * 256;
            int r = idx >> 2, c8 = (idx & 3) * 8;
            cp_async16(as_base + (uint32_t)(r * G_AST + c8) * 2u,
                       A + (size_t)(m0 + r) * K + k0 + c8);
        }
#pragma unroll
        for (int it = 0; it < 2; it++) {     // B: 128x32 halves
            int idx = tid + it * 256;
            int r = idx >> 2, c8 = (idx & 3) * 8;
            cp_async16(bs_base + (uint32_t)(r * G_AST + c8) * 2u,
                       Bt + (size_t)(n0 + r) * K + k0 + c8);
        }
    };

    float acc[2][8][4];
#pragma unroll
    for (int mt = 0; mt < 2; mt++)
#pragma unroll
        for (int nt = 0; nt < 8; nt++)
#pragma unroll
            for (int i = 0; i < 4; i++) acc[mt][nt][i] = 0.0f;

#pragma unroll
    for (int s = 0; s < G_NSTG - 1; s++) { load_stage(s, s); cp_commit(); }

    const int a_row_l = lane & 15, a_col_l = (lane >> 4) * 8;
    const int b_row_l = ((lane >> 4) << 3) + (lane & 7);
    const int b_col_l = ((lane >> 3) & 1) * 8;

    for (int j = 0; j < nk; j++) {
        cp_wait<G_NSTG - 2>();
        __syncthreads();
        if (j + G_NSTG - 1 < nk) {
            load_stage(j + G_NSTG - 1, (j + G_NSTG - 1) & (G_NSTG - 1));
            cp_commit();
        }
        const uint32_t as_u32 = smem_u32 + (uint32_t)((j & (G_NSTG - 1)) * G3_STG_H) * 2u;
        const uint32_t bs_u32 = as_u32 + (uint32_t)G3_AH * 2u;

#pragma unroll
        for (int ks = 0; ks < 2; ks++) {
            uint32_t a[2][4], bb[8][4];
#pragma unroll
            for (int mt = 0; mt < 2; mt++) {
                uint32_t addr = as_u32 +
                    (uint32_t)((wm + mt * 16 + a_row_l) * G_AST + ks * 16 + a_col_l) * 2u;
                ldsm_x4(addr, a[mt]);
            }
#pragma unroll
            for (int jj = 0; jj < 4; jj++) {
                uint32_t addr = bs_u32 +
                    (uint32_t)((wn + jj * 16 + b_row_l) * G_AST + ks * 16 + b_col_l) * 2u;
                uint32_t r4[4];
                ldsm_x4(addr, r4);
                bb[2 * jj][0] = r4[0]; bb[2 * jj][1] = r4[1];
                bb[2 * jj + 1][0] = r4[2]; bb[2 * jj + 1][1] = r4[3];
            }
#pragma unroll
            for (int mt = 0; mt < 2; mt++)
#pragma unroll
                for (int nt = 0; nt < 8; nt++)
                    mma_f16(acc[mt][nt], a[mt], bb[nt][0], bb[nt][1]);
        }
    }

#pragma unroll
    for (int mt = 0; mt < 2; mt++) {
        int row = m0 + wm + mt * 16 + g;
#pragma unroll
        for (int nt = 0; nt < 8; nt++) {
            int col = n0 + wn + nt * 8 + 2 * t;
            *(float2*)(C + (size_t)row * N + col) =
                make_float2(acc[mt][nt][0], acc[mt][nt][1]);
            *(float2*)(C + (size_t)(row + 8) * N + col) =
                make_float2(acc[mt][nt][2], acc[mt][nt][3]);
        }
    }
}

// ---------------------------------------------------------------------------
// fp16 fused SiLU-attention + normalizer + LayerNorm(64) + gate.
// Per-batch: base pointers pre-offset by the caller. Grid (S/128, NHEADS),
// 256 threads = 8 warps, warp owns 16 q rows (round-7 best config).
// ---------------------------------------------------------------------------
#define AT_ST   72
#define AT_QH   (128 * AT_ST)
#define AT_KH   (64 * AT_ST)
#define AT_VH   (64 * AT_ST)
#define AT_STGH (AT_KH + AT_VH)
#define ATT_SMEM_BYTES ((AT_QH + 2 * AT_STGH) * 2)   // 55296

__global__ void __launch_bounds__(256, 2) attn_kernel(
    const __half* __restrict__ P16b, const __half* __restrict__ mask16b,
    const float* __restrict__ invb,
    const float* __restrict__ gamma, const float* __restrict__ beta,
    __half* __restrict__ att16b)
{
    extern __shared__ __align__(16) __half sh[];
    __half* Qs = sh;

    const int tid = threadIdx.x, warp = tid >> 5, lane = tid & 31;
    const int g = lane >> 2, t = lane & 3;
    const int h = blockIdx.y;
    const int q0 = blockIdx.x * 128;
    const uint32_t smem_u32 = smem_u32_of(sh);

    const __half* qb  = P16b + h * HDIM;
    const __half* kb_ = qb + DM;
    const __half* vb_ = qb + 2 * DM;
    const __half* gb_ = qb + 3 * DM;

#pragma unroll
    for (int it = 0; it < 4; it++) {
        int idx = tid + it * 256;
        int r = idx >> 3, c8 = (idx & 7) * 8;
        *(uint4*)&Qs[r * AT_ST + c8] = *(const uint4*)(qb + (size_t)(q0 + r) * PCOLS + c8);
    }

    auto load_kv = [&](int kblk, int s) {
        const uint32_t kbs = smem_u32 + (uint32_t)(AT_QH + s * AT_STGH) * 2u;
        const uint32_t vbs = kbs + (uint32_t)AT_KH * 2u;
        const int k0 = kblk * 64;
#pragma unroll
        for (int it = 0; it < 2; it++) {
            int idx = tid + it * 256;
            int r = idx >> 3, c8 = (idx & 7) * 8;
            cp_async16(kbs + (uint32_t)(r * AT_ST + c8) * 2u,
                       kb_ + (size_t)(k0 + r) * PCOLS + c8);
            cp_async16(vbs + (uint32_t)(r * AT_ST + c8) * 2u,
                       vb_ + (size_t)(k0 + r) * PCOLS + c8);
        }
    };
    load_kv(0, 0); cp_commit();

    float o[8][4];
#pragma unroll
    for (int nt = 0; nt < 8; nt++)
#pragma unroll
        for (int i = 0; i < 4; i++) o[nt][i] = 0.0f;

    const int lrow = warp * 16 + g;
    const int a_row_l = lane & 15, a_col_l = (lane >> 4) * 8;
    const int b_row_l = ((lane >> 4) << 3) + (lane & 7);
    const int b_col_l = ((lane >> 3) & 1) * 8;

    for (int kb = 0; kb < 32; kb++) {
        cp_wait<0>();
        __syncthreads();
        if (kb + 1 < 32) { load_kv(kb + 1, (kb + 1) & 1); cp_commit(); }

        const uint32_t k_u32 = smem_u32 + (uint32_t)(AT_QH + (kb & 1) * AT_STGH) * 2u;
        const uint32_t v_u32 = k_u32 + (uint32_t)AT_KH * 2u;

        // ---- prefetch mask (consumed after S-mma; latency hidden) ----
        uint32_t pm0[8], pm1[8];
#pragma unroll
        for (int nt = 0; nt < 8; nt++) {
            const __half* mp = mask16b + (size_t)(q0 + lrow) * S_LEN + kb * 64 + nt * 8 + 2 * t;
            pm0[nt] = *(const uint32_t*)mp;
            pm1[nt] = *(const uint32_t*)(mp + 8 * S_LEN);
        }

        // ---- S = Q @ K^T ----
        float s[8][4];
#pragma unroll
        for (int nt = 0; nt < 8; nt++)
#pragma unroll
            for (int i = 0; i < 4; i++) s[nt][i] = 0.0f;

#pragma unroll
        for (int ks = 0; ks < 4; ks++) {
            uint32_t a[4];
            ldsm_x4(smem_u32 +
                (uint32_t)((warp * 16 + a_row_l) * AT_ST + ks * 16 + a_col_l) * 2u, a);
#pragma unroll
            for (int jj = 0; jj < 4; jj++) {
                uint32_t r4[4];
                ldsm_x4(k_u32 +
                    (uint32_t)((jj * 16 + b_row_l) * AT_ST + ks * 16 + b_col_l) * 2u, r4);
                mma_f16(s[2 * jj],     a, r4[0], r4[1]);
                mma_f16(s[2 * jj + 1], a, r4[2], r4[3]);
            }
        }

        // ---- silu * mask -> packed fp16 A-frags ----
        uint32_t p0[8], p1[8];
#pragma unroll
        for (int nt = 0; nt < 8; nt++) {
            __half2 v01 = __floats2half2_rn(fsilu(s[nt][0] * ATT_SCALE),
                                            fsilu(s[nt][1] * ATT_SCALE));
            __half2 v23 = __floats2half2_rn(fsilu(s[nt][2] * ATT_SCALE),
                                            fsilu(s[nt][3] * ATT_SCALE));
            p0[nt] = h2_u32(__hmul2(v01, u32_h2(pm0[nt])));
            p1[nt] = h2_u32(__hmul2(v23, u32_h2(pm1[nt])));
        }

        // ---- O += S @ V  (V frags via ldmatrix.x4.trans) ----
#pragma unroll
        for (int kk = 0; kk < 4; kk++) {
            uint32_t a[4] = { p0[2 * kk], p1[2 * kk], p0[2 * kk + 1], p1[2 * kk + 1] };
#pragma unroll
            for (int jj = 0; jj < 4; jj++) {
                uint32_t r4[4];
                ldsm_x4t(v_u32 +
                    (uint32_t)((16 * kk + a_row_l) * AT_ST + jj * 16 + a_col_l) * 2u, r4);
                mma_f16(o[2 * jj],     a, r4[0], r4[1]);
                mma_f16(o[2 * jj + 1], a, r4[2], r4[3]);
            }
        }
    }

    // ---- normalizer + LayerNorm(64) + gate + store ----
    const float inv0 = invb[q0 + lrow];
    const float inv1 = invb[q0 + lrow + 8];

    float sum0 = 0.f, sq0 = 0.f, sum1 = 0.f, sq1 = 0.f;
#pragma unroll
    for (int nt = 0; nt < 8; nt++) {
        o[nt][0] *= inv0; o[nt][1] *= inv0;
        o[nt][2] *= inv1; o[nt][3] *= inv1;
        sum0 += o[nt][0] + o[nt][1];
        sq0  += o[nt][0] * o[nt][0] + o[nt][1] * o[nt][1];
        sum1 += o[nt][2] + o[nt][3];
        sq1  += o[nt][2] * o[nt][2] + o[nt][3] * o[nt][3];
    }
    sum0 += __shfl_xor_sync(0xffffffffu, sum0, 1);
    sum0 += __shfl_xor_sync(0xffffffffu, sum0, 2);
    sq0  += __shfl_xor_sync(0xffffffffu, sq0, 1);
    sq0  += __shfl_xor_sync(0xffffffffu, sq0, 2);
    sum1 += __shfl_xor_sync(0xffffffffu, sum1, 1);
    sum1 += __shfl_xor_sync(0xffffffffu, sum1, 2);
    sq1  += __shfl_xor_sync(0xffffffffu, sq1, 1);
    sq1  += __shfl_xor_sync(0xffffffffu, sq1, 2);

    const float mu0 = sum0 * (1.0f / 64.0f);
    const float mu1 = sum1 * (1.0f / 64.0f);
    const float rs0 = rsqrtf(sq0 * (1.0f / 64.0f) - mu0 * mu0 + LN_EPS);
    const float rs1 = rsqrtf(sq1 * (1.0f / 64.0f) - mu1 * mu1 + LN_EPS);

    const int grow0 = q0 + lrow, grow1 = grow0 + 8;
#pragma unroll
    for (int nt = 0; nt < 8; nt++) {
        const int d = nt * 8 + 2 * t;
        const float ga0 = gamma[d], ga1 = gamma[d + 1];
        const float be0 = beta[d],  be1 = beta[d + 1];
        float2 gv0 = __half22float2(*(const __half2*)(gb_ + (size_t)grow0 * PCOLS + d));
        float2 gv1 = __half22float2(*(const __half2*)(gb_ + (size_t)grow1 * PCOLS + d));
        float w0 = ((o[nt][0] - mu0) * rs0 * ga0 + be0) * gv0.x;
        float w1 = ((o[nt][1] - mu0) * rs0 * ga1 + be1) * gv0.y;
        float w2 = ((o[nt][2] - mu1) * rs1 * ga0 + be0) * gv1.x;
        float w3 = ((o[nt][3] - mu1) * rs1 * ga1 + be1) * gv1.y;
        *(__half2*)(att16b + (size_t)grow0 * DM + h * HDIM + d) = __floats2half2_rn(w0, w1);
        *(__half2*)(att16b + (size_t)grow1 * DM + h * HDIM + d) = __floats2half2_rn(w2, w3);
    }
}

// ---------------------------------------------------------------------------
// Launch: round-14 graph (best measured): THREE streams.
//   s2  : mask_prep -> evM -> transposeWo -> evO          (prep only)
//   s1  : transposeW -> evW -> [wait evC] b1 chain -> evB
//   main: cvt16(all) -> evC -> [wait evW] b0 chain -> [wait evB]
// GEMM3 uses the 128x128-tile kernel (128 CTAs/batch, occ 2) for full-chip
// fill in the end tail.
// ---------------------------------------------------------------------------
extern "C" void kernel_launch(void* const* d_in, const int* in_sizes, int n_in,
                              void* d_out, int out_size)
{
    const float* tokens = (const float*)d_in[0];
    const int*   mask   = (const int*)d_in[1];
    const float* Wqkuv  = (const float*)d_in[2];
    const float* Wout   = (const float*)d_in[3];
    const float* gamma  = (const float*)d_in[4];
    const float* beta   = (const float*)d_in[5];
    float* out = (float*)d_out;

    __half *tok16, *Wt16, *Wo16T, *P16, *att16, *mask16;
    float* inv;
    cudaGetSymbolAddress((void**)&tok16,  g_tok16);
    cudaGetSymbolAddress((void**)&Wt16,   g_Wt16);
    cudaGetSymbolAddress((void**)&Wo16T,  g_Wo16T);
    cudaGetSymbolAddress((void**)&P16,    g_P16);
    cudaGetSymbolAddress((void**)&att16,  g_att16);
    cudaGetSymbolAddress((void**)&mask16, g_mask16);
    cudaGetSymbolAddress((void**)&inv,    g_inv);

    cudaFuncSetAttribute(gemm_f16_kernel, cudaFuncAttributeMaxDynamicSharedMemorySize,
                         GEMM_SMEM_BYTES);
    cudaFuncSetAttribute(gemm_f16_n128_kernel, cudaFuncAttributeMaxDynamicSharedMemorySize,
                         G3_SMEM_BYTES);
    cudaFuncSetAttribute(attn_kernel, cudaFuncAttributeMaxDynamicSharedMemorySize,
                         ATT_SMEM_BYTES);

    // one-time host-handle setup (host handles only; no device memory)
    static cudaStream_t s1 = nullptr, s2 = nullptr;
    static cudaEvent_t evF = nullptr, evC = nullptr, evW = nullptr,
                       evM = nullptr, evO = nullptr, evB = nullptr;
    if (s1 == nullptr) {
        cudaStreamCreateWithFlags(&s1, cudaStreamNonBlocking);
        cudaStreamCreateWithFlags(&s2, cudaStreamNonBlocking);
        cudaEventCreateWithFlags(&evF, cudaEventDisableTiming);
        cudaEventCreateWithFlags(&evC, cudaEventDisableTiming);
        cudaEventCreateWithFlags(&evW, cudaEventDisableTiming);
        cudaEventCreateWithFlags(&evM, cudaEventDisableTiming);
        cudaEventCreateWithFlags(&evO, cudaEventDisableTiming);
        cudaEventCreateWithFlags(&evB, cudaEventDisableTiming);
    }

    const size_t tokB = (size_t)S_LEN * DM;        // per-batch token elems
    const size_t pB   = (size_t)S_LEN * PCOLS;     // per-batch P elems
    const size_t mB   = (size_t)S_LEN * S_LEN;     // per-batch mask elems

    // fork
    cudaEventRecord(evF, 0);
    cudaStreamWaitEvent(s1, evF, 0);
    cudaStreamWaitEvent(s2, evF, 0);

    // ---- s2: prep-only branch ----
    mask_prep_kernel<<<BATCH * S_LEN, 256, 0, s2>>>(mask, mask16, inv);
    cudaEventRecord(evM, s2);
    transpose16_kernel<<<dim3(DM / 32, DM / 32), dim3(32, 8), 0, s2>>>(
        Wout, Wo16T, DM, DM);
    cudaEventRecord(evO, s2);

    // ---- s1: W transpose, then the full b1 chain ----
    transpose16_kernel<<<dim3(PCOLS / 32, DM / 32), dim3(32, 8), 0, s1>>>(
        Wqkuv, Wt16, DM, PCOLS);
    cudaEventRecord(evW, s1);

    // ---- main: token conversion (both batches) ----
    cvt16_kernel<<<(MROWS * DM) / 1024, 256>>>(tokens, tok16, MROWS * DM);
    cudaEventRecord(evC, 0);

    // ---- b1 chain on s1 ----
    cudaStreamWaitEvent(s1, evC, 0);
    gemm_f16_kernel<<<dim3(PCOLS / 256, S_LEN / 128), 512, GEMM_SMEM_BYTES, s1>>>(
        tok16 + tokB, Wt16, P16 + pB, S_LEN, PCOLS, DM, 1);
    cudaStreamWaitEvent(s1, evM, 0);
    attn_kernel<<<dim3(S_LEN / 128, NHEADS), 256, ATT_SMEM_BYTES, s1>>>(
        P16 + pB, mask16 + mB, inv + S_LEN, gamma, beta, att16 + tokB);
    cudaStreamWaitEvent(s1, evO, 0);
    gemm_f16_n128_kernel<<<dim3(DM / 128, S_LEN / 128), 256, G3_SMEM_BYTES, s1>>>(
        att16 + tokB, Wo16T, out + tokB, S_LEN, DM, DM);
    cudaEventRecord(evB, s1);

    // ---- b0 chain on main ----
    cudaStreamWaitEvent(0, evW, 0);
    gemm_f16_kernel<<<dim3(PCOLS / 256, S_LEN / 128), 512, GEMM_SMEM_BYTES>>>(
        tok16, Wt16, P16, S_LEN, PCOLS, DM, 1);
    cudaStreamWaitEvent(0, evM, 0);
    attn_kernel<<<dim3(S_LEN / 128, NHEADS), 256, ATT_SMEM_BYTES>>>(
        P16, mask16, inv, gamma, beta, att16);
    cudaStreamWaitEvent(0, evO, 0);
    gemm_f16_n128_kernel<<<dim3(DM / 128, S_LEN / 128), 256, G3_SMEM_BYTES>>>(
        att16, Wo16T, out, S_LEN, DM, DM);

    // join
    cudaStreamWaitEvent(0, evB, 0);
}